// round 13
// baseline (speedup 1.0000x reference)
#include <cuda_runtime.h>
#include <cuda_bf16.h>
#include <cuda_fp16.h>
#include <cstdint>

#define MAX_N 50000
#define MAX_E 800000
#define D 128

// Scratch in device globals.
__device__ int   g_is64;
__device__ int   g_deg[MAX_N];
__device__ int   g_off[MAX_N + 1];
__device__ int   g_cursor[MAX_N];
__device__ int   g_esrc[MAX_E];
__device__ int   g_bsum[64];
__device__ __align__(16) float  g_agg[(size_t)MAX_N * D];
__device__ __align__(16) float  g_h[(size_t)MAX_N * D];
__device__ __align__(16) __half g_xh[(size_t)MAX_N * D];   // fp16 x (gather source, layer 0)
__device__ __align__(16) __half g_hh[(size_t)MAX_N * D];   // fp16 h (gather source, layer 1)
__device__ __align__(16) __half g_w16[4 * D * D];          // fp16 Wl0,Wr0,Wl1,Wr1

// ---------------------------------------------------------------------------
// Base-ISA tensor primitives (harness PTX target is sm_103 WITHOUT 'a':
// tcgen05 unavailable; mma.sync/ldmatrix are the tensor path).
// ---------------------------------------------------------------------------
__device__ __forceinline__ uint32_t smem_u32(const void* p) {
    uint32_t a;
    asm("{ .reg .u64 t; cvta.to.shared.u64 t, %1; cvt.u32.u64 %0, t; }" : "=r"(a) : "l"(p));
    return a;
}

#define LDSM_X4(r0, r1, r2, r3, addr) \
    asm volatile("ldmatrix.sync.aligned.m8n8.x4.shared.b16 {%0,%1,%2,%3}, [%4];" \
                 : "=r"(r0), "=r"(r1), "=r"(r2), "=r"(r3) : "r"(addr))

#define MMAF16(c, a, b0, b1) \
    asm volatile("mma.sync.aligned.m16n8k16.row.col.f32.f16.f16.f32 " \
                 "{%0,%1,%2,%3}, {%4,%5,%6,%7}, {%8,%9}, {%0,%1,%2,%3};" \
                 : "+f"((c)[0]), "+f"((c)[1]), "+f"((c)[2]), "+f"((c)[3]) \
                 : "r"((a)[0]), "r"((a)[1]), "r"((a)[2]), "r"((a)[3]), \
                   "r"(b0), "r"(b1))

__device__ __forceinline__ uint2 pack_f16(float4 v) {
    __half2 p0 = __halves2half2(__float2half_rn(v.x), __float2half_rn(v.y));
    __half2 p1 = __halves2half2(__float2half_rn(v.z), __float2half_rn(v.w));
    uint2 u;
    u.x = *(uint32_t*)&p0; u.y = *(uint32_t*)&p1;
    return u;
}

// ---------------------------------------------------------------------------
// k_init: zero degrees + edge-dtype detect (dataset says int64, JAX default
// config emits int32 -> odd words all zero when truly int64).
// ---------------------------------------------------------------------------
__global__ void k_init(const int* __restrict__ ei32, int n) {
    int i = blockIdx.x * blockDim.x + threadIdx.x;
    if (i < n) g_deg[i] = 0;
    if (i == 0) {
        int allzero = 1;
        #pragma unroll
        for (int k = 1; k < 64; k += 2)
            if (ei32[k] != 0) allzero = 0;
        g_is64 = allzero;
    }
}

// Convert x -> fp16 gather source, weights -> fp16 (single rounding, same as
// the GEMM's previous per-CTA rounding; no extra accuracy loss for W).
__global__ void k_conv(const float* __restrict__ x,
                       const float* __restrict__ Wl0, const float* __restrict__ Wr0,
                       const float* __restrict__ Wl1, const float* __restrict__ Wr1,
                       int n) {
    int tid = blockIdx.x * blockDim.x + threadIdx.x;
    int stride = gridDim.x * blockDim.x;
    int total_x = n * (D / 4);
    for (int i = tid; i < total_x; i += stride)
        *(uint2*)&g_xh[(size_t)i * 4] = pack_f16(((const float4*)x)[i]);
    for (int i = tid; i < 4 * (D * D / 4); i += stride) {
        int w = i >> 12, j = i & 4095;
        const float* W = (w == 0) ? Wl0 : (w == 1) ? Wr0 : (w == 2) ? Wl1 : Wr1;
        *(uint2*)&g_w16[w * D * D + j * 4] = pack_f16(((const float4*)W)[j]);
    }
}

__device__ __forceinline__ int edge_at(const void* ei, int idx, int is64) {
    return is64 ? (int)((const long long*)ei)[idx] : ((const int*)ei)[idx];
}

__global__ void k_hist(const void* __restrict__ ei, int E) {
    int e = blockIdx.x * blockDim.x + threadIdx.x;
    int is64 = g_is64;
    if (e < E) atomicAdd(&g_deg[edge_at(ei, E + e, is64)], 1);
}

__global__ void k_scan_local(int n) {
    __shared__ int warp_sums[32];
    int lane = threadIdx.x & 31, wid = threadIdx.x >> 5;
    int i = blockIdx.x * 1024 + threadIdx.x;
    int v = (i < n) ? g_deg[i] : 0;
    int s = v;
    #pragma unroll
    for (int o = 1; o < 32; o <<= 1) {
        int t = __shfl_up_sync(0xFFFFFFFFu, s, o);
        if (lane >= o) s += t;
    }
    if (lane == 31) warp_sums[wid] = s;
    __syncthreads();
    if (wid == 0) {
        int ws = warp_sums[lane];
        #pragma unroll
        for (int o = 1; o < 32; o <<= 1) {
            int t = __shfl_up_sync(0xFFFFFFFFu, ws, o);
            if (lane >= o) ws += t;
        }
        warp_sums[lane] = ws;
    }
    __syncthreads();
    int incl = s + (wid > 0 ? warp_sums[wid - 1] : 0);
    if (i < n) g_off[i] = incl - v;
    if (threadIdx.x == 1023) g_bsum[blockIdx.x] = incl;
}

// Each block re-scans the <=64 block sums itself (no separate mid kernel).
__global__ void k_scan_add(int nb, int n) {
    __shared__ int spre, stot;
    if (threadIdx.x < 32) {
        int lane = threadIdx.x;
        int v0 = (lane < nb) ? g_bsum[lane] : 0;
        int v1 = (lane + 32 < nb) ? g_bsum[lane + 32] : 0;
        int s0 = v0;
        #pragma unroll
        for (int o = 1; o < 32; o <<= 1) {
            int t = __shfl_up_sync(0xFFFFFFFFu, s0, o);
            if (lane >= o) s0 += t;
        }
        int tot0 = __shfl_sync(0xFFFFFFFFu, s0, 31);
        int s1 = v1;
        #pragma unroll
        for (int o = 1; o < 32; o <<= 1) {
            int t = __shfl_up_sync(0xFFFFFFFFu, s1, o);
            if (lane >= o) s1 += t;
        }
        s1 += tot0;
        int b = blockIdx.x;
        int pre = 0;
        if (b > 0)
            pre = (b - 1 < 32) ? __shfl_sync(0xFFFFFFFFu, s0, b - 1)
                               : __shfl_sync(0xFFFFFFFFu, s1, b - 33);
        int last = nb - 1;
        int tot = (last < 32) ? __shfl_sync(0xFFFFFFFFu, s0, last)
                              : __shfl_sync(0xFFFFFFFFu, s1, last - 32);
        if (lane == 0) { spre = pre; stot = tot; }
    }
    __syncthreads();
    int i = blockIdx.x * 1024 + threadIdx.x;
    if (i < n) {
        int o = g_off[i] + spre;
        g_off[i] = o;
        g_cursor[i] = o;
    }
    if (blockIdx.x == 0 && threadIdx.x == 0) g_off[n] = stot;
}

__global__ void k_fill(const void* __restrict__ ei, int E) {
    int e = blockIdx.x * blockDim.x + threadIdx.x;
    int is64 = g_is64;
    if (e < E) {
        int s = edge_at(ei, e, is64);
        int d = edge_at(ei, E + e, is64);
        g_esrc[atomicAdd(&g_cursor[d], 1)] = s;
    }
}

// ---------------------------------------------------------------------------
// Aggregation: warp per node, fp16 gather (HALF the L2 bytes of fp32; this
// stage is LTS-byte-bound), fp32 accumulate -> g_agg.
// Do NOT fuse into GEMM: measured regression (161.9 -> 209us, R10).
// ---------------------------------------------------------------------------
__global__ void k_aggregate(int use_h, int n) {
    const __half* xin = use_h ? g_hh : g_xh;
    int warp = (blockIdx.x * blockDim.x + threadIdx.x) >> 5;
    int lane = threadIdx.x & 31;
    if (warp >= n) return;
    int s0 = g_off[warp];
    int s1 = g_off[warp + 1];
    float4 acc = make_float4(0.f, 0.f, 0.f, 0.f);
    int e = s0;
    for (; e + 2 <= s1; e += 2) {
        int srcA = g_esrc[e], srcB = g_esrc[e + 1];
        uint2 ua = *(const uint2*)(xin + (size_t)srcA * D + lane * 4);
        uint2 ub = *(const uint2*)(xin + (size_t)srcB * D + lane * 4);
        float2 a0 = __half22float2(*(__half2*)&ua.x);
        float2 a1 = __half22float2(*(__half2*)&ua.y);
        float2 b0 = __half22float2(*(__half2*)&ub.x);
        float2 b1 = __half22float2(*(__half2*)&ub.y);
        acc.x += a0.x + b0.x; acc.y += a0.y + b0.y;
        acc.z += a1.x + b1.x; acc.w += a1.y + b1.y;
    }
    if (e < s1) {
        int src = g_esrc[e];
        uint2 ua = *(const uint2*)(xin + (size_t)src * D + lane * 4);
        float2 a0 = __half22float2(*(__half2*)&ua.x);
        float2 a1 = __half22float2(*(__half2*)&ua.y);
        acc.x += a0.x; acc.y += a0.y; acc.z += a1.x; acc.w += a1.y;
    }
    int cnt = s1 - s0;
    float inv = (cnt > 0) ? (1.0f / (float)cnt) : 0.0f;
    acc.x *= inv; acc.y *= inv; acc.z *= inv; acc.w *= inv;
    *(float4*)(g_agg + (size_t)warp * D + lane * 4) = acc;
}

// ---------------------------------------------------------------------------
// Tensor-core GEMM via mma.sync fp16, fp32 acc. A (agg / X) split hi/lo
// exactly in fp16 (2 chains -> a·b_hi); W pre-rounded fp16 in g_w16.
// Tile M=128, N=128, K=128 resident, 2 passes share accumulators.
// 8 warps 4(M)x2(N). Smem 104448B, 2 CTAs/SM.
// Layer 0 epilogue also emits fp16 h (g_hh) for layer 1's gather.
// ---------------------------------------------------------------------------
#define SA 136
#define TILEB (128 * SA * 2)
#define OFF_AH 0
#define OFF_AL TILEB
#define OFF_BH (2 * TILEB)
#define SAGE_SMEM (3 * TILEB)          // 104448

__device__ __forceinline__ void pack_hilo_f16(float4 v, uint2* hu, uint2* lu) {
    __half h0 = __float2half_rn(v.x), h1 = __float2half_rn(v.y);
    __half h2 = __float2half_rn(v.z), h3 = __float2half_rn(v.w);
    __half l0 = __float2half_rn(v.x - __half2float(h0));
    __half l1 = __float2half_rn(v.y - __half2float(h1));
    __half l2 = __float2half_rn(v.z - __half2float(h2));
    __half l3 = __float2half_rn(v.w - __half2float(h3));
    __half2 hp0 = __halves2half2(h0, h1), hp1 = __halves2half2(h2, h3);
    __half2 lp0 = __halves2half2(l0, l1), lp1 = __halves2half2(l2, l3);
    hu->x = *(uint32_t*)&hp0; hu->y = *(uint32_t*)&hp1;
    lu->x = *(uint32_t*)&lp0; lu->y = *(uint32_t*)&lp1;
}

template <bool RELU>
__global__ void __launch_bounds__(256, 2)
k_gemm_mma(const float* __restrict__ Bext, int B_is_h, int wbase,
           const float* __restrict__ bias,
           float* __restrict__ outext, int out_is_h, int n) {
    extern __shared__ __align__(16) char sm[];
    __half* AH = (__half*)(sm + OFF_AH);
    __half* AL = (__half*)(sm + OFF_AL);
    __half* BH = (__half*)(sm + OFF_BH);

    const float* Bp = B_is_h ? (const float*)g_h : Bext;
    float* outp = out_is_h ? (float*)g_h : outext;

    const int tid = threadIdx.x;
    const int wid = tid >> 5;
    const int lane = tid & 31;
    const int warp_m = wid >> 1;
    const int warp_n = wid & 1;
    const int row0 = blockIdx.x * 128;

    float acc[2][8][4];
    #pragma unroll
    for (int t = 0; t < 2; t++)
        #pragma unroll
        for (int nt = 0; nt < 8; nt++)
            #pragma unroll
            for (int q = 0; q < 4; q++) acc[t][nt][q] = 0.f;

    #pragma unroll
    for (int pass = 0; pass < 2; pass++) {
        const float* X = pass ? Bp : (const float*)g_agg;
        const __half* W16 = g_w16 + (wbase + pass) * D * D;

        __syncthreads();
        // A tile: exact fp16 hi/lo split of fp32 source
        #pragma unroll 4
        for (int it = 0; it < 16; it++) {
            int idx = it * 256 + tid;
            int r = idx >> 5, c4 = (idx & 31) * 4;
            int gr = row0 + r;
            float4 v = make_float4(0.f, 0.f, 0.f, 0.f);
            if (gr < n) v = *(const float4*)(X + (size_t)gr * D + c4);
            uint2 hu, lu;
            pack_hilo_f16(v, &hu, &lu);
            *(uint2*)&AH[r * SA + c4] = hu;
            *(uint2*)&AL[r * SA + c4] = lu;
        }
        // B tile: copy pre-converted fp16 weights
        #pragma unroll 4
        for (int it = 0; it < 16; it++) {
            int idx = it * 256 + tid;
            int r = idx >> 5, c4 = (idx & 31) * 4;
            *(uint2*)&BH[r * SA + c4] = *(const uint2*)&W16[r * D + c4];
        }
        __syncthreads();

        #pragma unroll
        for (int ks = 0; ks < 8; ks++) {
            const int k0 = ks * 16;
            uint32_t ah[2][4], al[2][4];
            #pragma unroll
            for (int t = 0; t < 2; t++) {
                int mrow = warp_m * 32 + t * 16 + (lane & 15);
                int mcol = k0 + (lane >> 4) * 8;
                LDSM_X4(ah[t][0], ah[t][1], ah[t][2], ah[t][3],
                        smem_u32(&AH[mrow * SA + mcol]));
                LDSM_X4(al[t][0], al[t][1], al[t][2], al[t][3],
                        smem_u32(&AL[mrow * SA + mcol]));
            }
            #pragma unroll
            for (int np = 0; np < 4; np++) {
                int nn = warp_n * 64 + np * 16 + (lane & 7) + ((lane >> 4) << 3);
                int kk = k0 + ((lane >> 3) & 1) * 8;
                uint32_t bh0, bh1, bh2, bh3;
                LDSM_X4(bh0, bh1, bh2, bh3, smem_u32(&BH[nn * SA + kk]));
                #pragma unroll
                for (int t = 0; t < 2; t++) {
                    MMAF16(acc[t][np * 2], ah[t], bh0, bh1);
                    MMAF16(acc[t][np * 2], al[t], bh0, bh1);
                    MMAF16(acc[t][np * 2 + 1], ah[t], bh2, bh3);
                    MMAF16(acc[t][np * 2 + 1], al[t], bh2, bh3);
                }
            }
        }
    }

    // Epilogue; layer 0 also writes fp16 h for the next gather
    #pragma unroll
    for (int t = 0; t < 2; t++) {
        int rbase = row0 + warp_m * 32 + t * 16 + (lane >> 2);
        #pragma unroll
        for (int nt = 0; nt < 8; nt++) {
            int col = warp_n * 64 + nt * 8 + (lane & 3) * 2;
            float2 bb = *(const float2*)&bias[col];
            if (rbase < n) {
                float2 v;
                v.x = acc[t][nt][0] + bb.x;
                v.y = acc[t][nt][1] + bb.y;
                if (RELU) { v.x = fmaxf(v.x, 0.f); v.y = fmaxf(v.y, 0.f); }
                *(float2*)(outp + (size_t)rbase * D + col) = v;
                if (RELU)
                    *(__half2*)&g_hh[(size_t)rbase * D + col] = __floats2half2_rn(v.x, v.y);
            }
            if (rbase + 8 < n) {
                float2 v;
                v.x = acc[t][nt][2] + bb.x;
                v.y = acc[t][nt][3] + bb.y;
                if (RELU) { v.x = fmaxf(v.x, 0.f); v.y = fmaxf(v.y, 0.f); }
                *(float2*)(outp + (size_t)(rbase + 8) * D + col) = v;
                if (RELU)
                    *(__half2*)&g_hh[(size_t)(rbase + 8) * D + col] = __floats2half2_rn(v.x, v.y);
            }
        }
    }
}

// ---------------------------------------------------------------------------
extern "C" void kernel_launch(void* const* d_in, const int* in_sizes, int n_in,
                              void* d_out, int out_size) {
    const float* x   = (const float*)d_in[0];
    const void*  ei  = d_in[1];
    const float* Wl0 = (const float*)d_in[2];
    const float* bl0 = (const float*)d_in[3];
    const float* Wr0 = (const float*)d_in[4];
    const float* Wl1 = (const float*)d_in[5];
    const float* bl1 = (const float*)d_in[6];
    const float* Wr1 = (const float*)d_in[7];
    float*       out = (float*)d_out;

    const int n = in_sizes[0] / D;
    const int E = in_sizes[1] / 2;
    const int nb = (n + 1023) / 1024;

    static int attr_set = 0;
    if (!attr_set) {
        cudaFuncSetAttribute(k_gemm_mma<true>,
                             cudaFuncAttributeMaxDynamicSharedMemorySize, SAGE_SMEM);
        cudaFuncSetAttribute(k_gemm_mma<false>,
                             cudaFuncAttributeMaxDynamicSharedMemorySize, SAGE_SMEM);
        attr_set = 1;
    }

    // CSR build + one-time fp16 conversions
    k_init<<<(n + 255) / 256, 256>>>((const int*)ei, n);
    k_conv<<<(n * 32 + 255) / 256, 256>>>(x, Wl0, Wr0, Wl1, Wr1, n);
    k_hist<<<(E + 255) / 256, 256>>>(ei, E);
    k_scan_local<<<nb, 1024>>>(n);
    k_scan_add<<<nb, 1024>>>(nb, n);
    k_fill<<<(E + 255) / 256, 256>>>(ei, E);

    const int agg_blocks  = (n * 32 + 255) / 256;
    const int gemm_blocks = (n + 127) / 128;

    // Layer 0: g_h (+g_hh fp16) = relu(agg(x16) @ Wl0^T + b0 + x @ Wr0^T)
    k_aggregate<<<agg_blocks, 256>>>(0, n);
    k_gemm_mma<true><<<gemm_blocks, 256, SAGE_SMEM>>>(x, 0, 0, bl0, nullptr, 1, n);

    // Layer 1: out = agg(h16) @ Wl1^T + b1 + g_h @ Wr1^T
    k_aggregate<<<agg_blocks, 256>>>(1, n);
    k_gemm_mma<false><<<gemm_blocks, 256, SAGE_SMEM>>>(nullptr, 1, 2, bl1, out, 0, n);
}

// round 15
// speedup vs baseline: 1.0523x; 1.0523x over previous
#include <cuda_runtime.h>
#include <cuda_bf16.h>
#include <cuda_fp16.h>
#include <cstdint>

#define MAX_N 50000
#define MAX_E 800000
#define D 128
#define NCTA 296          // 2 x 148 SMs: always co-resident on sm_103a

// Scratch in device globals.
__device__ int   g_deg[MAX_N];
__device__ int   g_off[MAX_N + 1];
__device__ int   g_cursor[MAX_N];
__device__ int   g_esrc[MAX_E];
__device__ int   g_bsum[256];
__device__ unsigned g_cnt;                 // grid-barrier arrive counter
__device__ volatile unsigned g_gen;        // grid-barrier generation
__device__ __align__(16) float  g_agg[(size_t)MAX_N * D];
__device__ __align__(16) float  g_h[(size_t)MAX_N * D];
__device__ __align__(16) __half g_w16[4 * D * D];   // fp16 Wl0,Wr0,Wl1,Wr1

// ---------------------------------------------------------------------------
// Base-ISA tensor primitives (harness PTX target is sm_103 WITHOUT 'a':
// tcgen05 unavailable; mma.sync/ldmatrix are the tensor path).
// ---------------------------------------------------------------------------
__device__ __forceinline__ uint32_t smem_u32(const void* p) {
    uint32_t a;
    asm("{ .reg .u64 t; cvta.to.shared.u64 t, %1; cvt.u32.u64 %0, t; }" : "=r"(a) : "l"(p));
    return a;
}

#define LDSM_X4(r0, r1, r2, r3, addr) \
    asm volatile("ldmatrix.sync.aligned.m8n8.x4.shared.b16 {%0,%1,%2,%3}, [%4];" \
                 : "=r"(r0), "=r"(r1), "=r"(r2), "=r"(r3) : "r"(addr))

#define MMAF16(c, a, b0, b1) \
    asm volatile("mma.sync.aligned.m16n8k16.row.col.f32.f16.f16.f32 " \
                 "{%0,%1,%2,%3}, {%4,%5,%6,%7}, {%8,%9}, {%0,%1,%2,%3};" \
                 : "+f"((c)[0]), "+f"((c)[1]), "+f"((c)[2]), "+f"((c)[3]) \
                 : "r"((a)[0]), "r"((a)[1]), "r"((a)[2]), "r"((a)[3]), \
                   "r"(b0), "r"(b1))

__device__ __forceinline__ uint2 pack_f16(float4 v) {
    __half2 p0 = __halves2half2(__float2half_rn(v.x), __float2half_rn(v.y));
    __half2 p1 = __halves2half2(__float2half_rn(v.z), __float2half_rn(v.w));
    uint2 u;
    u.x = *(uint32_t*)&p0; u.y = *(uint32_t*)&p1;
    return u;
}

__device__ __forceinline__ int edge_at(const void* ei, int idx, int is64) {
    return is64 ? (int)((const long long*)ei)[idx] : ((const int*)ei)[idx];
}

// Grid-wide barrier: all NCTA CTAs are resident by construction.
__device__ __forceinline__ void gbar(int nctas) {
    __syncthreads();
    if (threadIdx.x == 0) {
        __threadfence();
        unsigned old = g_gen;
        if (atomicAdd(&g_cnt, 1u) == (unsigned)(nctas - 1)) {
            g_cnt = 0;
            __threadfence();
            g_gen = old + 1;                  // release
        } else {
            while (g_gen == old) { }          // spin (L2 poll)
        }
    }
    __syncthreads();
}

// Block-wide (256 thr) exclusive scan; also returns block total.
__device__ __forceinline__ int block_scan256(int v, int* tot, int* ws) {
    int lane = threadIdx.x & 31, w = threadIdx.x >> 5;
    int s = v;
    #pragma unroll
    for (int o = 1; o < 32; o <<= 1) {
        int t = __shfl_up_sync(0xFFFFFFFFu, s, o);
        if (lane >= o) s += t;
    }
    if (lane == 31) ws[w] = s;
    __syncthreads();
    if (w == 0) {
        int t = (lane < 8) ? ws[lane] : 0;
        #pragma unroll
        for (int o = 1; o < 8; o <<= 1) {
            int u = __shfl_up_sync(0xFFFFFFFFu, t, o);
            if (lane >= o) t += u;
        }
        if (lane < 8) ws[lane] = t;
    }
    __syncthreads();
    int pre = (w > 0) ? ws[w - 1] : 0;
    *tot = ws[7];
    __syncthreads();                          // ws reusable by caller afterwards
    return s + pre - v;                       // exclusive
}

// ---------------------------------------------------------------------------
// ONE kernel for the whole CSR build (+ W->fp16), phases separated by
// grid-wide barriers. Replaces 6 launches (init/conv/hist/scan x2/fill).
// ---------------------------------------------------------------------------
__global__ void __launch_bounds__(256)
k_csr(const void* __restrict__ ei, int E, int n,
      const float* __restrict__ Wl0, const float* __restrict__ Wr0,
      const float* __restrict__ Wl1, const float* __restrict__ Wr1) {
    __shared__ int s_is64;
    __shared__ int s_ws[8];
    __shared__ int s_pre;
    const int tid = threadIdx.x;
    const int cta = blockIdx.x;
    const int nctas = gridDim.x;
    const int gtid = cta * 256 + tid;
    const int gstride = nctas * 256;

    // --- Phase A: dtype detect + zero degrees + W -> fp16 ---
    if (tid < 32) {
        int w = ((const int*)ei)[2 * tid + 1];
        unsigned b = __ballot_sync(0xFFFFFFFFu, w == 0);
        if (tid == 0) s_is64 = (b == 0xFFFFFFFFu) ? 1 : 0;
    }
    for (int i = gtid; i < n; i += gstride) g_deg[i] = 0;
    for (int i = gtid; i < 4 * (D * D / 4); i += gstride) {
        int w = i >> 12, j = i & 4095;
        const float* W = (w == 0) ? Wl0 : (w == 1) ? Wr0 : (w == 2) ? Wl1 : Wr1;
        *(uint2*)&g_w16[w * D * D + j * 4] = pack_f16(((const float4*)W)[j]);
    }
    __syncthreads();
    const int is64 = s_is64;
    gbar(nctas);

    // --- Phase B: degree histogram ---
    for (int e = gtid; e < E; e += gstride)
        atomicAdd(&g_deg[edge_at(ei, E + e, is64)], 1);
    gbar(nctas);

    // --- Phase C: local scan, one 256-chunk per CTA ---
    const int nch = (n + 255) >> 8;           // 196 for n=50000
    {
        int i = cta * 256 + tid;
        int v = (cta < nch && i < n) ? g_deg[i] : 0;
        int tot;
        int excl = block_scan256(v, &tot, s_ws);
        if (cta < nch) {
            if (i < n) g_off[i] = excl;
            if (tid == 0) g_bsum[cta] = tot;
        }
    }
    gbar(nctas);

    // --- Phase D: redundant per-CTA scan of block sums + add + cursor ---
    {
        int v = (tid < nch) ? g_bsum[tid] : 0;
        int tot;
        int excl = block_scan256(v, &tot, s_ws);
        if (tid == cta) s_pre = excl;         // cta < nch < 256 when used
        __syncthreads();
        if (cta < nch) {
            int pre = s_pre;
            int i = cta * 256 + tid;
            if (i < n) {
                int o = g_off[i] + pre;
                g_off[i] = o;
                g_cursor[i] = o;
            }
        }
        if (cta == 0 && tid == 0) g_off[n] = tot;
    }
    gbar(nctas);

    // --- Phase E: fill edge sources ---
    for (int e = gtid; e < E; e += gstride) {
        int s = edge_at(ei, e, is64);
        int d = edge_at(ei, E + e, is64);
        g_esrc[atomicAdd(&g_cursor[d], 1)] = s;
    }
}

// ---------------------------------------------------------------------------
// Aggregation: warp per node (max parallelism), fp32 gather (fp16 gather was
// a measured non-win, R13), 4-edge unroll for MLP. Do NOT fuse into GEMM
// (measured regression R10).
// ---------------------------------------------------------------------------
__global__ void k_aggregate(const float* __restrict__ xext, int use_h, int n) {
    const float* xin = use_h ? (const float*)g_h : xext;
    int warp = (blockIdx.x * blockDim.x + threadIdx.x) >> 5;
    int lane = threadIdx.x & 31;
    if (warp >= n) return;
    int s0 = g_off[warp];
    int s1 = g_off[warp + 1];
    float4 acc = make_float4(0.f, 0.f, 0.f, 0.f);
    int e = s0;
    for (; e + 4 <= s1; e += 4) {             // 4 independent gathers in flight
        int i0 = g_esrc[e], i1 = g_esrc[e + 1], i2 = g_esrc[e + 2], i3 = g_esrc[e + 3];
        float4 a = *(const float4*)(xin + (size_t)i0 * D + lane * 4);
        float4 b = *(const float4*)(xin + (size_t)i1 * D + lane * 4);
        float4 c = *(const float4*)(xin + (size_t)i2 * D + lane * 4);
        float4 d = *(const float4*)(xin + (size_t)i3 * D + lane * 4);
        acc.x += (a.x + b.x) + (c.x + d.x);
        acc.y += (a.y + b.y) + (c.y + d.y);
        acc.z += (a.z + b.z) + (c.z + d.z);
        acc.w += (a.w + b.w) + (c.w + d.w);
    }
    for (; e < s1; e++) {
        int src = g_esrc[e];
        float4 a = *(const float4*)(xin + (size_t)src * D + lane * 4);
        acc.x += a.x; acc.y += a.y; acc.z += a.z; acc.w += a.w;
    }
    int cnt = s1 - s0;
    float inv = (cnt > 0) ? (1.0f / (float)cnt) : 0.0f;
    acc.x *= inv; acc.y *= inv; acc.z *= inv; acc.w *= inv;
    *(float4*)(g_agg + (size_t)warp * D + lane * 4) = acc;
}

// ---------------------------------------------------------------------------
// Tensor-core GEMM via mma.sync fp16, fp32 acc. A split hi/lo exactly in fp16
// (2 chains -> a·b_hi, dropped a·b_lo ~ 1e-4 rel); W pre-rounded fp16 (g_w16).
// Tile M=128, N=128, K=128 resident, 2 passes share accumulators.
// 8 warps 4(M)x2(N). Smem 104448B, 2 CTAs/SM.
// ---------------------------------------------------------------------------
#define SA 136
#define TILEB (128 * SA * 2)
#define OFF_AH 0
#define OFF_AL TILEB
#define OFF_BH (2 * TILEB)
#define SAGE_SMEM (3 * TILEB)          // 104448

__device__ __forceinline__ void pack_hilo_f16(float4 v, uint2* hu, uint2* lu) {
    __half h0 = __float2half_rn(v.x), h1 = __float2half_rn(v.y);
    __half h2 = __float2half_rn(v.z), h3 = __float2half_rn(v.w);
    __half l0 = __float2half_rn(v.x - __half2float(h0));
    __half l1 = __float2half_rn(v.y - __half2float(h1));
    __half l2 = __float2half_rn(v.z - __half2float(h2));
    __half l3 = __float2half_rn(v.w - __half2float(h3));
    __half2 hp0 = __halves2half2(h0, h1), hp1 = __halves2half2(h2, h3);
    __half2 lp0 = __halves2half2(l0, l1), lp1 = __halves2half2(l2, l3);
    hu->x = *(uint32_t*)&hp0; hu->y = *(uint32_t*)&hp1;
    lu->x = *(uint32_t*)&lp0; lu->y = *(uint32_t*)&lp1;
}

template <bool RELU>
__global__ void __launch_bounds__(256, 2)
k_gemm_mma(const float* __restrict__ Bext, int B_is_h, int wbase,
           const float* __restrict__ bias,
           float* __restrict__ outext, int out_is_h, int n) {
    extern __shared__ __align__(16) char sm[];
    __half* AH = (__half*)(sm + OFF_AH);
    __half* AL = (__half*)(sm + OFF_AL);
    __half* BH = (__half*)(sm + OFF_BH);

    const float* Bp = B_is_h ? (const float*)g_h : Bext;
    float* outp = out_is_h ? (float*)g_h : outext;

    const int tid = threadIdx.x;
    const int wid = tid >> 5;
    const int lane = tid & 31;
    const int warp_m = wid >> 1;
    const int warp_n = wid & 1;
    const int row0 = blockIdx.x * 128;

    float acc[2][8][4];
    #pragma unroll
    for (int t = 0; t < 2; t++)
        #pragma unroll
        for (int nt = 0; nt < 8; nt++)
            #pragma unroll
            for (int q = 0; q < 4; q++) acc[t][nt][q] = 0.f;

    #pragma unroll
    for (int pass = 0; pass < 2; pass++) {
        const float* X = pass ? Bp : (const float*)g_agg;
        const __half* W16 = g_w16 + (wbase + pass) * D * D;

        __syncthreads();
        // A tile: exact fp16 hi/lo split of fp32 source
        #pragma unroll 4
        for (int it = 0; it < 16; it++) {
            int idx = it * 256 + tid;
            int r = idx >> 5, c4 = (idx & 31) * 4;
            int gr = row0 + r;
            float4 v = make_float4(0.f, 0.f, 0.f, 0.f);
            if (gr < n) v = *(const float4*)(X + (size_t)gr * D + c4);
            uint2 hu, lu;
            pack_hilo_f16(v, &hu, &lu);
            *(uint2*)&AH[r * SA + c4] = hu;
            *(uint2*)&AL[r * SA + c4] = lu;
        }
        // B tile: copy pre-converted fp16 weights
        #pragma unroll 4
        for (int it = 0; it < 16; it++) {
            int idx = it * 256 + tid;
            int r = idx >> 5, c4 = (idx & 31) * 4;
            *(uint2*)&BH[r * SA + c4] = *(const uint2*)&W16[r * D + c4];
        }
        __syncthreads();

        #pragma unroll
        for (int ks = 0; ks < 8; ks++) {
            const int k0 = ks * 16;
            uint32_t ah[2][4], al[2][4];
            #pragma unroll
            for (int t = 0; t < 2; t++) {
                int mrow = warp_m * 32 + t * 16 + (lane & 15);
                int mcol = k0 + (lane >> 4) * 8;
                LDSM_X4(ah[t][0], ah[t][1], ah[t][2], ah[t][3],
                        smem_u32(&AH[mrow * SA + mcol]));
                LDSM_X4(al[t][0], al[t][1], al[t][2], al[t][3],
                        smem_u32(&AL[mrow * SA + mcol]));
            }
            #pragma unroll
            for (int np = 0; np < 4; np++) {
                int nn = warp_n * 64 + np * 16 + (lane & 7) + ((lane >> 4) << 3);
                int kk = k0 + ((lane >> 3) & 1) * 8;
                uint32_t bh0, bh1, bh2, bh3;
                LDSM_X4(bh0, bh1, bh2, bh3, smem_u32(&BH[nn * SA + kk]));
                #pragma unroll
                for (int t = 0; t < 2; t++) {
                    MMAF16(acc[t][np * 2], ah[t], bh0, bh1);
                    MMAF16(acc[t][np * 2], al[t], bh0, bh1);
                    MMAF16(acc[t][np * 2 + 1], ah[t], bh2, bh3);
                    MMAF16(acc[t][np * 2 + 1], al[t], bh2, bh3);
                }
            }
        }
    }

    // Epilogue
    #pragma unroll
    for (int t = 0; t < 2; t++) {
        int rbase = row0 + warp_m * 32 + t * 16 + (lane >> 2);
        #pragma unroll
        for (int nt = 0; nt < 8; nt++) {
            int col = warp_n * 64 + nt * 8 + (lane & 3) * 2;
            float2 bb = *(const float2*)&bias[col];
            if (rbase < n) {
                float2 v;
                v.x = acc[t][nt][0] + bb.x;
                v.y = acc[t][nt][1] + bb.y;
                if (RELU) { v.x = fmaxf(v.x, 0.f); v.y = fmaxf(v.y, 0.f); }
                *(float2*)(outp + (size_t)rbase * D + col) = v;
            }
            if (rbase + 8 < n) {
                float2 v;
                v.x = acc[t][nt][2] + bb.x;
                v.y = acc[t][nt][3] + bb.y;
                if (RELU) { v.x = fmaxf(v.x, 0.f); v.y = fmaxf(v.y, 0.f); }
                *(float2*)(outp + (size_t)(rbase + 8) * D + col) = v;
            }
        }
    }
}

// ---------------------------------------------------------------------------
extern "C" void kernel_launch(void* const* d_in, const int* in_sizes, int n_in,
                              void* d_out, int out_size) {
    const float* x   = (const float*)d_in[0];
    const void*  ei  = d_in[1];
    const float* Wl0 = (const float*)d_in[2];
    const float* bl0 = (const float*)d_in[3];
    const float* Wr0 = (const float*)d_in[4];
    const float* Wl1 = (const float*)d_in[5];
    const float* bl1 = (const float*)d_in[6];
    const float* Wr1 = (const float*)d_in[7];
    float*       out = (float*)d_out;

    const int n = in_sizes[0] / D;
    const int E = in_sizes[1] / 2;

    static int attr_set = 0;
    if (!attr_set) {
        cudaFuncSetAttribute(k_gemm_mma<true>,
                             cudaFuncAttributeMaxDynamicSharedMemorySize, SAGE_SMEM);
        cudaFuncSetAttribute(k_gemm_mma<false>,
                             cudaFuncAttributeMaxDynamicSharedMemorySize, SAGE_SMEM);
        attr_set = 1;
    }

    // 1 launch: entire CSR build + W conversion (grid-barrier phased)
    k_csr<<<NCTA, 256>>>(ei, E, n, Wl0, Wr0, Wl1, Wr1);

    const int agg_blocks  = (n * 32 + 255) / 256;
    const int gemm_blocks = (n + 127) / 128;

    // Layer 0: g_h = relu(agg(x) @ Wl0^T + b0 + x @ Wr0^T)
    k_aggregate<<<agg_blocks, 256>>>(x, 0, n);
    k_gemm_mma<true><<<gemm_blocks, 256, SAGE_SMEM>>>(x, 0, 0, bl0, nullptr, 1, n);

    // Layer 1: out = agg(g_h) @ Wl1^T + b1 + g_h @ Wr1^T
    k_aggregate<<<agg_blocks, 256>>>(nullptr, 1, n);
    k_gemm_mma<false><<<gemm_blocks, 256, SAGE_SMEM>>>(nullptr, 1, 2, bl1, out, 0, n);
}